// round 2
// baseline (speedup 1.0000x reference)
#include <cuda_runtime.h>
#include <cuda_bf16.h>
#include <math.h>

#define BB 8
#define PP 2048
#define CC 21
#define CENTER_VAR 0.1f
#define SIZE_VAR 0.2f
#define GEPS 1e-8f

#define NBLK 64
#define NTHR 256

// Scratch (device globals)
__device__ float4 g_boxA[BB][PP];
__device__ float4 g_boxT[BB][PP];
__device__ int    g_cntA[BB];
__device__ int    g_cntT[BB];
__device__ float  g_S[BB];
__device__ int    g_is64;
__device__ unsigned g_bar;   // monotonic grid-barrier ticket counter

// Software grid barrier. Safe because all NBLK blocks are co-resident
// (NBLK=64 < 148 SMs, wave-1). Monotonic counter works across graph replays.
__device__ __forceinline__ void grid_barrier() {
    __syncthreads();
    if (threadIdx.x == 0) {
        __threadfence();                       // publish this block's writes
        unsigned t = atomicAdd(&g_bar, 1u);
        unsigned target = (t / NBLK + 1u) * NBLK;
        while (*((volatile unsigned*)&g_bar) < target) { __nanosleep(32); }
        __threadfence();
    }
    __syncthreads();
}

__global__ void __launch_bounds__(NTHR, 1)
iou_loss_fused(const float* __restrict__ conf,
               const float* __restrict__ loc,
               const int*   __restrict__ tc,
               const float* __restrict__ tloc,
               const float* __restrict__ priors,
               float* __restrict__ out) {
    const int tid  = threadIdx.x;
    const int bid  = blockIdx.x;
    const int gtid = bid * NTHR + tid;

    // ---------------- Phase 0: reset + dtype probe (block 0) ----------------
    if (bid == 0) {
        if (tid < BB) { g_cntA[tid] = 0; g_cntT[tid] = 0; g_S[tid] = 0.f; }
        __syncthreads();
        if (tid == 0) {
            // target_confidence values are {0,1}. If int64 (LE), all odd
            // 32-bit words over first 256 words are zero.
            int any_odd = 0;
            #pragma unroll 4
            for (int i = 0; i < 128; i++) any_odd |= tc[2 * i + 1];
            g_is64 = (any_odd == 0) ? 1 : 0;
        }
    }
    grid_barrier();

    // ---------------- Phase 1: classify + decode + compact ------------------
    {
        const int idx = gtid;                 // exactly BB*PP threads
        const int b = idx >> 11;              // /PP
        const int p = idx & (PP - 1);
        const int is64 = g_is64;
        int tv = is64 ? tc[2 * idx] : tc[idx];
        if (tv > 0) {
            float4 pr = ((const float4*)priors)[p];

            // decode target box -> T list
            {
                float4 l = ((const float4*)tloc)[idx];
                float cx = pr.x + l.x * CENTER_VAR * pr.z;
                float cy = pr.y + l.y * CENTER_VAR * pr.w;
                float w  = pr.z * __expf(l.z * SIZE_VAR);
                float h  = pr.w * __expf(l.w * SIZE_VAR);
                float x0 = cx - 0.5f * w;
                float y0 = cy - 0.5f * h;
                int s = atomicAdd(&g_cntT[b], 1);
                g_boxT[b][s] = make_float4(x0, y0, x0 + w, y0 + h);
            }

            // softmax max-prob + argmax
            const float* cf = conf + (size_t)idx * CC;
            float m = cf[0];
            int mi = 0;
            #pragma unroll
            for (int c = 1; c < CC; c++) {
                float v = cf[c];
                if (v > m) { m = v; mi = c; }
            }
            float se = 0.f;
            #pragma unroll
            for (int c = 0; c < CC; c++) se += expf(cf[c] - m);
            float maxp = 1.f / se;

            if (maxp > 0.5f && mi > 0) {
                float4 l = ((const float4*)loc)[idx];
                float cx = pr.x + l.x * CENTER_VAR * pr.z;
                float cy = pr.y + l.y * CENTER_VAR * pr.w;
                float w  = pr.z * __expf(l.z * SIZE_VAR);
                float h  = pr.w * __expf(l.w * SIZE_VAR);
                float x0 = cx - 0.5f * w;
                float y0 = cy - 0.5f * h;
                int s = atomicAdd(&g_cntA[b], 1);
                g_boxA[b][s] = make_float4(x0, y0, x0 + w, y0 + h);
            }
        }
    }
    grid_barrier();

    // ---------------- Phase 2: pairwise GIoU sum -----------------------------
    {
        const int b = bid & (BB - 1);         // 8 blocks per batch
        const int blk_in_b = bid >> 3;        // 0..7
        const int nA = g_cntA[b];
        const int nT = g_cntT[b];
        if (nA > 0 && nT > 0) {
            __shared__ float4 sT[NTHR];
            float acc = 0.f;
            for (int t0 = 0; t0 < nT; t0 += NTHR) {
                int cnt = min(NTHR, nT - t0);
                __syncthreads();
                if (tid < cnt) sT[tid] = g_boxT[b][t0 + tid];
                __syncthreads();
                for (int a = blk_in_b * NTHR + tid; a < nA; a += 8 * NTHR) {
                    float4 A = g_boxA[b][a];
                    float areaA = (A.z - A.x) * (A.w - A.y);
                    for (int j = 0; j < cnt; j++) {
                        float4 T = sT[j];
                        float ix = fminf(A.z, T.z) - fmaxf(A.x, T.x);
                        float iy = fminf(A.w, T.w) - fmaxf(A.y, T.y);
                        float inter = fmaxf(ix, 0.f) * fmaxf(iy, 0.f);
                        float areaT = (T.z - T.x) * (T.w - T.y);
                        float uni = areaA + areaT - inter;
                        float iou = inter / fmaxf(uni, GEPS);
                        float ex = fmaxf(A.z, T.z) - fminf(A.x, T.x);
                        float ey = fmaxf(A.w, T.w) - fminf(A.y, T.y);
                        float enc = ex * ey;
                        acc += iou - (enc - uni) / fmaxf(enc, GEPS);
                    }
                }
            }
            #pragma unroll
            for (int o = 16; o > 0; o >>= 1)
                acc += __shfl_down_sync(0xFFFFFFFFu, acc, o);
            if ((tid & 31) == 0 && acc != 0.f) atomicAdd(&g_S[b], acc);
        }
    }
    grid_barrier();

    // ---------------- Phase 3: finalize --------------------------------------
    if (bid == 0 && tid == 0) {
        float tsum = 0.f, ntsum = 0.f;
        #pragma unroll
        for (int b = 0; b < BB; b++) {
            float nt = (float)g_cntT[b];
            float na = (float)g_cntA[b];
            bool bt = nt > 0.f, ba = na > 0.f;
            float term;
            if (bt && ba)      term = nt - g_S[b] / fmaxf(nt, 1.f);
            else if (bt != ba) term = 1.f;
            else               term = 0.f;
            tsum += term;
            ntsum += nt;
        }
        out[0] = tsum / fmaxf(ntsum, 1.f);
    }
}

extern "C" void kernel_launch(void* const* d_in, const int* in_sizes, int n_in,
                              void* d_out, int out_size) {
    const float* conf   = (const float*)d_in[0];
    const float* loc    = (const float*)d_in[1];
    const int*   tc     = (const int*)d_in[2];
    const float* tloc   = (const float*)d_in[3];
    const float* priors = (const float*)d_in[4];
    float* out = (float*)d_out;

    iou_loss_fused<<<NBLK, NTHR>>>(conf, loc, tc, tloc, priors, out);
}

// round 3
// speedup vs baseline: 1.9824x; 1.9824x over previous
#include <cuda_runtime.h>
#include <cuda_bf16.h>
#include <math.h>

#define BB 8
#define PP 2048
#define CC 21
#define CENTER_VAR 0.1f
#define SIZE_VAR 0.2f
#define GEPS 1e-8f

#define NBLK 32
#define NTHR 256
#define GSZ  (NBLK * NTHR)          // 8192 threads
#define ITEMS ((BB * PP) / GSZ)     // 2 items per thread

// Scratch (device globals; zero at module load; reset by last block each run)
__device__ float4   g_boxA[BB][PP];
__device__ float4   g_boxT[BB][PP];
__device__ int      g_cntA[BB];
__device__ int      g_cntT[BB];
__device__ float    g_S[BB];
__device__ unsigned g_bar;   // monotonic: grid barrier tickets
__device__ unsigned g_fin;   // monotonic: finalize tickets

__device__ __forceinline__ float4 decode_box(float4 l, float4 pr) {
    float cx = pr.x + l.x * CENTER_VAR * pr.z;
    float cy = pr.y + l.y * CENTER_VAR * pr.w;
    float w  = pr.z * __expf(l.z * SIZE_VAR);
    float h  = pr.w * __expf(l.w * SIZE_VAR);
    float x0 = cx - 0.5f * w;
    float y0 = cy - 0.5f * h;
    return make_float4(x0, y0, x0 + w, y0 + h);
}

__global__ void __launch_bounds__(NTHR, 1)
iou_loss_fused(const float* __restrict__ conf,
               const float* __restrict__ loc,
               const int*   __restrict__ tc,
               const float* __restrict__ tloc,
               const float* __restrict__ priors,
               float* __restrict__ out) {
    const int tid  = threadIdx.x;
    const int bid  = blockIdx.x;
    const int lane = tid & 31;

    // ---- Phase 0: block-local int64/int32 probe (no grid sync needed) ------
    // target_confidence values are {0,1}. If int64 (LE), odd 32-bit words of
    // the first 256 words are all zero; if int32, P(all zero) ~ 2^-128.
    int w0 = (tid < 128) ? tc[2 * tid + 1] : 0;
    const bool is64 = (__syncthreads_or(w0) == 0);

    // ---- Phase 1: classify + decode + warp-aggregated compaction -----------
    #pragma unroll
    for (int i = 0; i < ITEMS; i++) {
        const int idx = bid * NTHR + tid + i * GSZ;   // warp stays in one batch
        const int b = idx >> 11;
        const int p = idx & (PP - 1);

        int tv = is64 ? tc[2 * idx] : tc[idx];
        bool isT = (tv > 0);
        bool isA = false;
        float4 boxT, boxA;

        if (isT) {
            float4 pr = ((const float4*)priors)[p];
            boxT = decode_box(((const float4*)tloc)[idx], pr);

            const float* cf = conf + (size_t)idx * CC;
            float m = cf[0]; int mi = 0;
            #pragma unroll
            for (int c = 1; c < CC; c++) {
                float v = cf[c];
                if (v > m) { m = v; mi = c; }
            }
            float se = 0.f;
            #pragma unroll
            for (int c = 0; c < CC; c++) se += expf(cf[c] - m);

            if (se < 2.0f && mi > 0) {               // maxp = 1/se > 0.5
                isA = true;
                boxA = decode_box(((const float4*)loc)[idx], pr);
            }
        }

        unsigned mT = __ballot_sync(0xffffffffu, isT);
        if (mT) {
            int ldr = __ffs(mT) - 1, base;
            if (lane == ldr) base = atomicAdd(&g_cntT[b], __popc(mT));
            base = __shfl_sync(0xffffffffu, base, ldr);
            if (isT)
                g_boxT[b][base + __popc(mT & ((1u << lane) - 1u))] = boxT;
        }
        unsigned mA = __ballot_sync(0xffffffffu, isA);
        if (mA) {
            int ldr = __ffs(mA) - 1, base;
            if (lane == ldr) base = atomicAdd(&g_cntA[b], __popc(mA));
            base = __shfl_sync(0xffffffffu, base, ldr);
            if (isA)
                g_boxA[b][base + __popc(mA & ((1u << lane) - 1u))] = boxA;
        }
    }

    // ---- Grid barrier (all NBLK blocks co-resident; monotonic ticket) ------
    __threadfence();            // publish this thread's box writes gpu-wide
    __syncthreads();
    if (tid == 0) {
        unsigned t = atomicAdd(&g_bar, 1u);
        unsigned target = (t / NBLK + 1u) * NBLK;
        while (*((volatile unsigned*)&g_bar) < target) { }
        __threadfence();
    }
    __syncthreads();

    // ---- Phase 2: flattened pairwise GIoU over k in [0, sum nA*nT) ---------
    __shared__ int s_cT[BB];
    __shared__ int s_off[BB + 1];
    if (tid < BB) s_cT[tid] = g_cntT[tid];
    __syncthreads();
    if (tid == 0) {
        int o = 0;
        #pragma unroll
        for (int b = 0; b < BB; b++) { s_off[b] = o; o += g_cntA[b] * s_cT[b]; }
        s_off[BB] = o;
    }
    __syncthreads();

    const int total = s_off[BB];
    for (int k = bid * NTHR + tid; k < total; k += GSZ) {
        int b = 0;
        #pragma unroll
        for (int q = 1; q < BB; q++) b += (k >= s_off[q]);
        int lk = k - s_off[b];
        int nt = s_cT[b];
        int a  = lk / nt;
        int t  = lk - a * nt;

        float4 A = g_boxA[b][a];
        float4 T = g_boxT[b][t];
        float ix = fminf(A.z, T.z) - fmaxf(A.x, T.x);
        float iy = fminf(A.w, T.w) - fmaxf(A.y, T.y);
        float inter = fmaxf(ix, 0.f) * fmaxf(iy, 0.f);
        float areaA = (A.z - A.x) * (A.w - A.y);
        float areaT = (T.z - T.x) * (T.w - T.y);
        float uni = areaA + areaT - inter;
        float iou = __fdividef(inter, fmaxf(uni, GEPS));
        float ex = fmaxf(A.z, T.z) - fminf(A.x, T.x);
        float ey = fmaxf(A.w, T.w) - fminf(A.y, T.y);
        float enc = ex * ey;
        float g = iou - __fdividef(enc - uni, fmaxf(enc, GEPS));
        atomicAdd(&g_S[b], g);
    }

    // ---- Finalize in the last-arriving block (monotonic ticket) ------------
    __threadfence();
    __syncthreads();
    __shared__ int s_last;
    if (tid == 0) {
        unsigned tk = atomicAdd(&g_fin, 1u);
        s_last = ((tk & (NBLK - 1u)) == (NBLK - 1u)) ? 1 : 0;
        if (s_last) __threadfence();
    }
    __syncthreads();

    if (s_last && tid < 32) {
        float term = 0.f, ntv = 0.f;
        if (tid < BB) {
            float nt = (float)g_cntT[tid];
            float na = (float)g_cntA[tid];
            bool bt = nt > 0.f, ba = na > 0.f;
            if (bt && ba)      term = nt - g_S[tid] / fmaxf(nt, 1.f);
            else if (bt != ba) term = 1.f;
            else               term = 0.f;
            ntv = nt;
        }
        #pragma unroll
        for (int o = 4; o > 0; o >>= 1) {
            term += __shfl_down_sync(0xffffffffu, term, o);
            ntv  += __shfl_down_sync(0xffffffffu, ntv, o);
        }
        if (tid == 0) out[0] = term / fmaxf(ntv, 1.f);
        // reset scratch for the next graph replay
        if (tid < BB) { g_cntA[tid] = 0; g_cntT[tid] = 0; g_S[tid] = 0.f; }
    }
}

extern "C" void kernel_launch(void* const* d_in, const int* in_sizes, int n_in,
                              void* d_out, int out_size) {
    const float* conf   = (const float*)d_in[0];
    const float* loc    = (const float*)d_in[1];
    const int*   tc     = (const int*)d_in[2];
    const float* tloc   = (const float*)d_in[3];
    const float* priors = (const float*)d_in[4];
    float* out = (float*)d_out;

    iou_loss_fused<<<NBLK, NTHR>>>(conf, loc, tc, tloc, priors, out);
}

// round 4
// speedup vs baseline: 2.0174x; 1.0177x over previous
#include <cuda_runtime.h>
#include <cuda_bf16.h>
#include <math.h>

#define BB 8
#define PP 2048
#define CC 21
#define CENTER_VAR 0.1f
#define SIZE_VAR 0.2f
#define GEPS 1e-8f

#define NBLK 64
#define NTHR 256
#define GSZ  (NBLK * NTHR)          // 16384 = BB*PP, one item per thread

// Scratch (device globals; zeroed at load; reset by last block each run)
__device__ float4   g_boxA[BB][PP];
__device__ float4   g_boxT[BB][PP];
__device__ int      g_cntA[BB];
__device__ int      g_cntT[BB];
__device__ float    g_S[BB];
__device__ unsigned g_bar;   // monotonic grid-barrier tickets
__device__ unsigned g_fin;   // monotonic finalize tickets

__device__ __forceinline__ float4 decode_box(float4 l, float4 pr) {
    float cx = pr.x + l.x * CENTER_VAR * pr.z;
    float cy = pr.y + l.y * CENTER_VAR * pr.w;
    float w  = pr.z * __expf(l.z * SIZE_VAR);
    float h  = pr.w * __expf(l.w * SIZE_VAR);
    float x0 = cx - 0.5f * w;
    float y0 = cy - 0.5f * h;
    return make_float4(x0, y0, x0 + w, y0 + h);
}

__global__ void __launch_bounds__(NTHR, 1)
iou_loss_fused(const float* __restrict__ conf,
               const float* __restrict__ loc,
               const int*   __restrict__ tc,
               const float* __restrict__ tloc,
               const float* __restrict__ priors,
               float* __restrict__ out) {
    const int tid  = threadIdx.x;
    const int bid  = blockIdx.x;
    const int lane = tid & 31;
    const int idx  = bid * NTHR + tid;     // exactly BB*PP threads
    const int b    = idx >> 11;
    const int p    = idx & (PP - 1);

    // ---- Front-batched unconditional loads (single DRAM latency exposure) --
    float4 pr = ((const float4*)priors)[p];
    float4 lt = ((const float4*)tloc)[idx];
    float4 ll = ((const float4*)loc)[idx];
    float  cf[CC];
    {
        const float* crow = conf + (size_t)idx * CC;
        #pragma unroll
        for (int c = 0; c < CC; c++) cf[c] = crow[c];
    }

    // ---- dtype probe (block-local). int64 LE {0,1} -> odd words all zero ---
    int w0 = (tid < 128) ? tc[2 * tid + 1] : 0;
    const bool is64 = (__syncthreads_or(w0) == 0);
    const int tv = is64 ? tc[2 * idx] : tc[idx];

    // ---- Unconditional compute -------------------------------------------
    float4 boxT = decode_box(lt, pr);
    float4 boxA = decode_box(ll, pr);

    float m = cf[0]; int mi = 0;
    #pragma unroll
    for (int c = 1; c < CC; c++) {
        float v = cf[c];
        if (v > m) { m = v; mi = c; }
    }
    float se = 0.f;
    #pragma unroll
    for (int c = 0; c < CC; c++) se += __expf(cf[c] - m);
    if (fabsf(se - 2.0f) < 1e-3f) {   // threshold guard: redo in full precision
        se = 0.f;
        #pragma unroll
        for (int c = 0; c < CC; c++) se += expf(cf[c] - m);
    }

    const bool isT = (tv > 0);
    const bool isA = isT && (se < 2.0f) && (mi > 0);   // maxp = 1/se > 0.5

    // ---- Warp-aggregated compaction (warp spans one batch: 256|2048) ------
    unsigned mT = __ballot_sync(0xffffffffu, isT);
    if (mT) {
        int ldr = __ffs(mT) - 1, base;
        if (lane == ldr) base = atomicAdd(&g_cntT[b], __popc(mT));
        base = __shfl_sync(0xffffffffu, base, ldr);
        if (isT) g_boxT[b][base + __popc(mT & ((1u << lane) - 1u))] = boxT;
    }
    unsigned mA = __ballot_sync(0xffffffffu, isA);
    if (mA) {
        int ldr = __ffs(mA) - 1, base;
        if (lane == ldr) base = atomicAdd(&g_cntA[b], __popc(mA));
        base = __shfl_sync(0xffffffffu, base, ldr);
        if (isA) g_boxA[b][base + __popc(mA & ((1u << lane) - 1u))] = boxA;
    }

    // ---- Grid barrier (all 64 blocks wave-1 co-resident) -------------------
    __threadfence();
    __syncthreads();
    if (tid == 0) {
        unsigned t = atomicAdd(&g_bar, 1u);
        unsigned target = (t / NBLK + 1u) * NBLK;
        while (*((volatile unsigned*)&g_bar) < target) { }
        __threadfence();
    }
    __syncthreads();

    // ---- Phase 2: flattened pairwise GIoU over k in [0, sum nA*nT) --------
    __shared__ int s_cT[BB];
    __shared__ int s_nA[BB];
    __shared__ int s_off[BB + 1];
    if (tid < BB) { s_cT[tid] = g_cntT[tid]; s_nA[tid] = g_cntA[tid]; }
    __syncthreads();
    if (tid == 0) {
        int o = 0;
        #pragma unroll
        for (int q = 0; q < BB; q++) { s_off[q] = o; o += s_nA[q] * s_cT[q]; }
        s_off[BB] = o;
    }
    __syncthreads();

    const int total = s_off[BB];
    for (int k = idx; k < total; k += GSZ) {
        int bb = 0;
        #pragma unroll
        for (int q = 1; q < BB; q++) bb += (k >= s_off[q]);
        int lk = k - s_off[bb];
        int nt = s_cT[bb];
        int a  = lk / nt;
        int t  = lk - a * nt;

        float4 A = g_boxA[bb][a];
        float4 T = g_boxT[bb][t];
        float ix = fminf(A.z, T.z) - fmaxf(A.x, T.x);
        float iy = fminf(A.w, T.w) - fmaxf(A.y, T.y);
        float inter = fmaxf(ix, 0.f) * fmaxf(iy, 0.f);
        float areaA = (A.z - A.x) * (A.w - A.y);
        float areaT = (T.z - T.x) * (T.w - T.y);
        float uni = areaA + areaT - inter;
        float iou = __fdividef(inter, fmaxf(uni, GEPS));
        float ex = fmaxf(A.z, T.z) - fminf(A.x, T.x);
        float ey = fmaxf(A.w, T.w) - fminf(A.y, T.y);
        float enc = ex * ey;
        float g = iou - __fdividef(enc - uni, fmaxf(enc, GEPS));
        atomicAdd(&g_S[bb], g);
    }

    // ---- Finalize in last-arriving block -----------------------------------
    __threadfence();
    __syncthreads();
    __shared__ int s_last;
    if (tid == 0) {
        unsigned tk = atomicAdd(&g_fin, 1u);
        s_last = ((tk & (NBLK - 1u)) == (NBLK - 1u)) ? 1 : 0;
        if (s_last) __threadfence();
    }
    __syncthreads();

    if (s_last && tid < 32) {
        float term = 0.f, ntv = 0.f;
        if (tid < BB) {
            float nt = (float)g_cntT[tid];
            float na = (float)g_cntA[tid];
            bool bt = nt > 0.f, ba = na > 0.f;
            if (bt && ba)      term = nt - g_S[tid] / fmaxf(nt, 1.f);
            else if (bt != ba) term = 1.f;
            else               term = 0.f;
            ntv = nt;
        }
        #pragma unroll
        for (int o = 4; o > 0; o >>= 1) {
            term += __shfl_down_sync(0xffffffffu, term, o);
            ntv  += __shfl_down_sync(0xffffffffu, ntv, o);
        }
        if (tid == 0) out[0] = term / fmaxf(ntv, 1.f);
        // reset scratch for next graph replay
        if (tid < BB) { g_cntA[tid] = 0; g_cntT[tid] = 0; g_S[tid] = 0.f; }
    }
}

extern "C" void kernel_launch(void* const* d_in, const int* in_sizes, int n_in,
                              void* d_out, int out_size) {
    const float* conf   = (const float*)d_in[0];
    const float* loc    = (const float*)d_in[1];
    const int*   tc     = (const int*)d_in[2];
    const float* tloc   = (const float*)d_in[3];
    const float* priors = (const float*)d_in[4];
    float* out = (float*)d_out;

    iou_loss_fused<<<NBLK, NTHR>>>(conf, loc, tc, tloc, priors, out);
}

// round 5
// speedup vs baseline: 2.0362x; 1.0093x over previous
#include <cuda_runtime.h>
#include <cuda_bf16.h>
#include <math.h>

#define BB 8
#define PP 2048
#define CC 21
#define CENTER_VAR 0.1f
#define SIZE_VAR 0.2f
#define GEPS 1e-8f

#define NBLK 64
#define NTHR 256
#define GSZ  (NBLK * NTHR)          // 16384 = BB*PP, one item per thread

// Scratch (device globals; zeroed at load; reset by finalizer each run)
__device__ float4   g_boxA[BB][PP];
__device__ float4   g_boxT[BB][PP];
__device__ int      g_cntA[BB];
__device__ int      g_cntT[BB];
__device__ float    g_S[BB];
__device__ unsigned g_bar;   // monotonic grid-barrier tickets
__device__ unsigned g_fin;   // monotonic finalize tickets

__device__ __forceinline__ float4 decode_box(float4 l, float4 pr) {
    float cx = pr.x + l.x * CENTER_VAR * pr.z;
    float cy = pr.y + l.y * CENTER_VAR * pr.w;
    float w  = pr.z * __expf(l.z * SIZE_VAR);
    float h  = pr.w * __expf(l.w * SIZE_VAR);
    float x0 = cx - 0.5f * w;
    float y0 = cy - 0.5f * h;
    return make_float4(x0, y0, x0 + w, y0 + h);
}

__device__ __forceinline__ void finalize_and_reset(const int* cT, const int* nAv,
                                                   bool need_S, float* out) {
    // caller guarantees: single warp, counts valid, g_S visible if need_S
    int l = threadIdx.x & 31;
    float term = 0.f, ntv = 0.f;
    if (l < BB) {
        float nt = (float)cT[l];
        float na = (float)nAv[l];
        bool bt = nt > 0.f, ba = na > 0.f;
        if (bt && ba)      term = nt - (need_S ? g_S[l] : 0.f) / fmaxf(nt, 1.f);
        else if (bt != ba) term = 1.f;
        else               term = 0.f;
        ntv = nt;
    }
    #pragma unroll
    for (int o = 4; o > 0; o >>= 1) {
        term += __shfl_down_sync(0xffffffffu, term, o);
        ntv  += __shfl_down_sync(0xffffffffu, ntv, o);
    }
    if (l == 0) out[0] = term / fmaxf(ntv, 1.f);
    if (l < BB) { g_cntA[l] = 0; g_cntT[l] = 0; g_S[l] = 0.f; }
}

__global__ void __launch_bounds__(NTHR, 1)
iou_loss_fused(const float* __restrict__ conf,
               const float* __restrict__ loc,
               const int*   __restrict__ tc,
               const float* __restrict__ tloc,
               const float* __restrict__ priors,
               float* __restrict__ out) {
    const int tid  = threadIdx.x;
    const int bid  = blockIdx.x;
    const int lane = tid & 31;
    const int idx  = bid * NTHR + tid;     // exactly BB*PP threads
    const int b    = idx >> 11;
    const int p    = idx & (PP - 1);

    // ---- Front-batched unconditional loads ---------------------------------
    float4 pr = ((const float4*)priors)[p];
    float4 lt = ((const float4*)tloc)[idx];
    float4 ll = ((const float4*)loc)[idx];
    float  cf[CC];
    {
        const float* crow = conf + (size_t)idx * CC;
        #pragma unroll
        for (int c = 0; c < CC; c++) cf[c] = crow[c];
    }

    // ---- dtype probe (block-local). int64 LE {0,1} -> odd words all zero ---
    int w0 = (tid < 128) ? tc[2 * tid + 1] : 0;
    const bool is64 = (__syncthreads_or(w0) == 0);
    const int tv = is64 ? tc[2 * idx] : tc[idx];

    // ---- Unconditional compute ---------------------------------------------
    float4 boxT = decode_box(lt, pr);
    float4 boxA = decode_box(ll, pr);

    float m = cf[0]; int mi = 0;
    #pragma unroll
    for (int c = 1; c < CC; c++) {
        float v = cf[c];
        if (v > m) { m = v; mi = c; }
    }
    float se = 0.f;
    #pragma unroll
    for (int c = 0; c < CC; c++) se += __expf(cf[c] - m);
    if (fabsf(se - 2.0f) < 1e-3f) {   // threshold guard: redo in full precision
        se = 0.f;
        #pragma unroll
        for (int c = 0; c < CC; c++) se += expf(cf[c] - m);
    }

    const bool isT = (tv > 0);
    const bool isA = isT && (se < 2.0f) && (mi > 0);   // maxp = 1/se > 0.5

    // ---- Warp-aggregated compaction ----------------------------------------
    unsigned mT = __ballot_sync(0xffffffffu, isT);
    if (mT) {
        int ldr = __ffs(mT) - 1, base;
        if (lane == ldr) base = atomicAdd(&g_cntT[b], __popc(mT));
        base = __shfl_sync(0xffffffffu, base, ldr);
        if (isT) g_boxT[b][base + __popc(mT & ((1u << lane) - 1u))] = boxT;
    }
    unsigned mA = __ballot_sync(0xffffffffu, isA);
    if (mA) {
        int ldr = __ffs(mA) - 1, base;
        if (lane == ldr) base = atomicAdd(&g_cntA[b], __popc(mA));
        base = __shfl_sync(0xffffffffu, base, ldr);
        if (isA) g_boxA[b][base + __popc(mA & ((1u << lane) - 1u))] = boxA;
    }

    // ---- Grid barrier: CTA release via bar.sync, fence+atomic in tid0 only -
    __syncthreads();
    if (tid == 0) {
        __threadfence();                           // cumulative: publishes block writes
        unsigned t = atomicAdd(&g_bar, 1u);
        unsigned target = (t / NBLK + 1u) * NBLK;
        while (*((volatile unsigned*)&g_bar) < target) { __nanosleep(64); }
        __threadfence();                           // acquire for the block
    }
    __syncthreads();

    // ---- Phase 2 setup ------------------------------------------------------
    __shared__ int s_cT[BB];
    __shared__ int s_nA[BB];
    __shared__ int s_off[BB + 1];
    if (tid < BB) { s_cT[tid] = g_cntT[tid]; s_nA[tid] = g_cntA[tid]; }
    __syncthreads();
    if (tid == 0) {
        int o = 0;
        #pragma unroll
        for (int q = 0; q < BB; q++) { s_off[q] = o; o += s_nA[q] * s_cT[q]; }
        s_off[BB] = o;
    }
    __syncthreads();
    const int total = s_off[BB];

    // ---- Fast path: no pairs anywhere -> block 0 finalizes, everyone exits -
    if (total == 0) {
        if (bid == 0 && tid < 32) finalize_and_reset(s_cT, s_nA, false, out);
        return;
    }

    // ---- Phase 2: flattened pairwise GIoU over k in [0, total) -------------
    for (int k = idx; k < total; k += GSZ) {
        int bb = 0;
        #pragma unroll
        for (int q = 1; q < BB; q++) bb += (k >= s_off[q]);
        int lk = k - s_off[bb];
        int nt = s_cT[bb];
        int a  = lk / nt;
        int t  = lk - a * nt;

        float4 A = g_boxA[bb][a];
        float4 T = g_boxT[bb][t];
        float ix = fminf(A.z, T.z) - fmaxf(A.x, T.x);
        float iy = fminf(A.w, T.w) - fmaxf(A.y, T.y);
        float inter = fmaxf(ix, 0.f) * fmaxf(iy, 0.f);
        float areaA = (A.z - A.x) * (A.w - A.y);
        float areaT = (T.z - T.x) * (T.w - T.y);
        float uni = areaA + areaT - inter;
        float iou = __fdividef(inter, fmaxf(uni, GEPS));
        float ex = fmaxf(A.z, T.z) - fminf(A.x, T.x);
        float ey = fmaxf(A.w, T.w) - fminf(A.y, T.y);
        float enc = ex * ey;
        float g = iou - __fdividef(enc - uni, fmaxf(enc, GEPS));
        atomicAdd(&g_S[bb], g);
    }

    // ---- Finalize in last-arriving block (tid0-only fence) -----------------
    __syncthreads();
    __shared__ int s_last;
    if (tid == 0) {
        __threadfence();                           // publish this block's g_S adds
        unsigned tk = atomicAdd(&g_fin, 1u);
        s_last = ((tk & (NBLK - 1u)) == (NBLK - 1u)) ? 1 : 0;
        if (s_last) __threadfence();               // acquire all g_S
    }
    __syncthreads();

    if (s_last && tid < 32) finalize_and_reset(s_cT, s_nA, true, out);
}

extern "C" void kernel_launch(void* const* d_in, const int* in_sizes, int n_in,
                              void* d_out, int out_size) {
    const float* conf   = (const float*)d_in[0];
    const float* loc    = (const float*)d_in[1];
    const int*   tc     = (const int*)d_in[2];
    const float* tloc   = (const float*)d_in[3];
    const float* priors = (const float*)d_in[4];
    float* out = (float*)d_out;

    iou_loss_fused<<<NBLK, NTHR>>>(conf, loc, tc, tloc, priors, out);
}

// round 6
// speedup vs baseline: 2.0504x; 1.0070x over previous
#include <cuda_runtime.h>
#include <cuda_bf16.h>
#include <math.h>

#define BB 8
#define PP 2048
#define CC 21
#define CENTER_VAR 0.1f
#define SIZE_VAR 0.2f
#define GEPS 1e-8f

#define NBLK 64
#define NTHR 256
#define NWARP (NTHR / 32)
#define GSZ  (NBLK * NTHR)          // 16384 = BB*PP, one item per thread

// Scratch (device globals; zeroed at load; reset by finalizer each run)
__device__ float4   g_boxA[BB][PP];
__device__ float4   g_boxT[BB][PP];
__device__ int      g_cntA[BB];
__device__ int      g_cntT[BB];
__device__ float    g_S[BB];
__device__ unsigned g_bar;   // monotonic grid-barrier tickets
__device__ unsigned g_fin;   // monotonic finalize tickets

__device__ __forceinline__ float4 decode_box(float4 l, float4 pr) {
    float cx = pr.x + l.x * CENTER_VAR * pr.z;
    float cy = pr.y + l.y * CENTER_VAR * pr.w;
    float w  = pr.z * __expf(l.z * SIZE_VAR);
    float h  = pr.w * __expf(l.w * SIZE_VAR);
    float x0 = cx - 0.5f * w;
    float y0 = cy - 0.5f * h;
    return make_float4(x0, y0, x0 + w, y0 + h);
}

__device__ __forceinline__ void finalize_and_reset(const int* cT, const int* nAv,
                                                   bool need_S, float* out) {
    int l = threadIdx.x & 31;
    float term = 0.f, ntv = 0.f;
    if (l < BB) {
        float nt = (float)cT[l];
        float na = (float)nAv[l];
        bool bt = nt > 0.f, ba = na > 0.f;
        if (bt && ba)      term = nt - (need_S ? g_S[l] : 0.f) / fmaxf(nt, 1.f);
        else if (bt != ba) term = 1.f;
        else               term = 0.f;
        ntv = nt;
    }
    #pragma unroll
    for (int o = 4; o > 0; o >>= 1) {
        term += __shfl_down_sync(0xffffffffu, term, o);
        ntv  += __shfl_down_sync(0xffffffffu, ntv, o);
    }
    if (l == 0) out[0] = term / fmaxf(ntv, 1.f);
    if (l < BB) { g_cntA[l] = 0; g_cntT[l] = 0; g_S[l] = 0.f; }
}

__global__ void __launch_bounds__(NTHR, 1)
iou_loss_fused(const float* __restrict__ conf,
               const float* __restrict__ loc,
               const int*   __restrict__ tc,
               const float* __restrict__ tloc,
               const float* __restrict__ priors,
               float* __restrict__ out) {
    const int tid  = threadIdx.x;
    const int bid  = blockIdx.x;
    const int lane = tid & 31;
    const int wid  = tid >> 5;
    const int idx  = bid * NTHR + tid;     // exactly BB*PP threads
    const int b    = idx >> 11;
    const int p    = idx & (PP - 1);

    // ---- Warp-coalesced conf staging into smem ------------------------------
    // Each warp copies its 32 rows (32*21 = 672 floats = 168 float4, 16B
    // aligned) with fully-coalesced float4 loads, then threads read their own
    // row from smem (stride 21 is coprime to 32 -> bank-conflict-free).
    __shared__ float s_conf[NWARP][32 * CC];
    {
        const float4* g4 = (const float4*)(conf + (size_t)(bid * NTHR + wid * 32) * CC);
        float4* s4 = (float4*)s_conf[wid];
        #pragma unroll
        for (int i = 0; i < 6; i++) {
            int j = i * 32 + lane;
            if (j < (32 * CC) / 4) s4[j] = g4[j];
        }
    }

    // ---- Other front-batched loads (overlap with staging) ------------------
    float4 pr = ((const float4*)priors)[p];
    float4 lt = ((const float4*)tloc)[idx];
    float4 ll = ((const float4*)loc)[idx];

    // ---- dtype probe (block-local). int64 LE {0,1} -> odd words all zero ---
    int w0 = (tid < 128) ? tc[2 * tid + 1] : 0;
    const bool is64 = (__syncthreads_or(w0) == 0);   // also orders smem staging
    const int tv = is64 ? tc[2 * idx] : tc[idx];

    // ---- Unconditional compute ----------------------------------------------
    float4 boxT = decode_box(lt, pr);
    float4 boxA = decode_box(ll, pr);

    const float* cf = &s_conf[wid][lane * CC];
    float m = cf[0]; int mi = 0;
    #pragma unroll
    for (int c = 1; c < CC; c++) {
        float v = cf[c];
        if (v > m) { m = v; mi = c; }
    }
    float se = 0.f;
    #pragma unroll
    for (int c = 0; c < CC; c++) se += __expf(cf[c] - m);
    if (fabsf(se - 2.0f) < 1e-3f) {   // threshold guard: redo in full precision
        se = 0.f;
        #pragma unroll
        for (int c = 0; c < CC; c++) se += expf(cf[c] - m);
    }

    const bool isT = (tv > 0);
    const bool isA = isT && (se < 2.0f) && (mi > 0);   // maxp = 1/se > 0.5

    // ---- Warp-aggregated compaction -----------------------------------------
    unsigned mT = __ballot_sync(0xffffffffu, isT);
    if (mT) {
        int ldr = __ffs(mT) - 1, base;
        if (lane == ldr) base = atomicAdd(&g_cntT[b], __popc(mT));
        base = __shfl_sync(0xffffffffu, base, ldr);
        if (isT) g_boxT[b][base + __popc(mT & ((1u << lane) - 1u))] = boxT;
    }
    unsigned mA = __ballot_sync(0xffffffffu, isA);
    if (mA) {
        int ldr = __ffs(mA) - 1, base;
        if (lane == ldr) base = atomicAdd(&g_cntA[b], __popc(mA));
        base = __shfl_sync(0xffffffffu, base, ldr);
        if (isA) g_boxA[b][base + __popc(mA & ((1u << lane) - 1u))] = boxA;
    }

    // ---- Grid barrier: fence+atomic in tid0 only ----------------------------
    __syncthreads();
    if (tid == 0) {
        __threadfence();
        unsigned t = atomicAdd(&g_bar, 1u);
        unsigned target = (t / NBLK + 1u) * NBLK;
        while (*((volatile unsigned*)&g_bar) < target) { __nanosleep(64); }
        __threadfence();
    }
    __syncthreads();

    // ---- Phase 2 setup -------------------------------------------------------
    __shared__ int s_cT[BB];
    __shared__ int s_nA[BB];
    __shared__ int s_off[BB + 1];
    if (tid < BB) { s_cT[tid] = g_cntT[tid]; s_nA[tid] = g_cntA[tid]; }
    __syncthreads();
    if (tid == 0) {
        int o = 0;
        #pragma unroll
        for (int q = 0; q < BB; q++) { s_off[q] = o; o += s_nA[q] * s_cT[q]; }
        s_off[BB] = o;
    }
    __syncthreads();
    const int total = s_off[BB];

    // ---- Fast path: no pairs anywhere -> block 0 finalizes ------------------
    if (total == 0) {
        if (bid == 0 && tid < 32) finalize_and_reset(s_cT, s_nA, false, out);
        return;
    }

    // ---- Phase 2: flattened pairwise GIoU over k in [0, total) --------------
    for (int k = idx; k < total; k += GSZ) {
        int bb = 0;
        #pragma unroll
        for (int q = 1; q < BB; q++) bb += (k >= s_off[q]);
        int lk = k - s_off[bb];
        int nt = s_cT[bb];
        int a  = lk / nt;
        int t  = lk - a * nt;

        float4 A = g_boxA[bb][a];
        float4 T = g_boxT[bb][t];
        float ix = fminf(A.z, T.z) - fmaxf(A.x, T.x);
        float iy = fminf(A.w, T.w) - fmaxf(A.y, T.y);
        float inter = fmaxf(ix, 0.f) * fmaxf(iy, 0.f);
        float areaA = (A.z - A.x) * (A.w - A.y);
        float areaT = (T.z - T.x) * (T.w - T.y);
        float uni = areaA + areaT - inter;
        float iou = __fdividef(inter, fmaxf(uni, GEPS));
        float ex = fmaxf(A.z, T.z) - fminf(A.x, T.x);
        float ey = fmaxf(A.w, T.w) - fminf(A.y, T.y);
        float enc = ex * ey;
        float g = iou - __fdividef(enc - uni, fmaxf(enc, GEPS));
        atomicAdd(&g_S[bb], g);
    }

    // ---- Finalize in last-arriving block -------------------------------------
    __syncthreads();
    __shared__ int s_last;
    if (tid == 0) {
        __threadfence();
        unsigned tk = atomicAdd(&g_fin, 1u);
        s_last = ((tk & (NBLK - 1u)) == (NBLK - 1u)) ? 1 : 0;
        if (s_last) __threadfence();
    }
    __syncthreads();

    if (s_last && tid < 32) finalize_and_reset(s_cT, s_nA, true, out);
}

extern "C" void kernel_launch(void* const* d_in, const int* in_sizes, int n_in,
                              void* d_out, int out_size) {
    const float* conf   = (const float*)d_in[0];
    const float* loc    = (const float*)d_in[1];
    const int*   tc     = (const int*)d_in[2];
    const float* tloc   = (const float*)d_in[3];
    const float* priors = (const float*)d_in[4];
    float* out = (float*)d_out;

    iou_loss_fused<<<NBLK, NTHR>>>(conf, loc, tc, tloc, priors, out);
}